// round 17
// baseline (speedup 1.0000x reference)
#include <cuda_runtime.h>
#include <cuda_fp16.h>
#include <mma.h>
#include <cstdint>

using namespace nvcuda;

// ---------------------------------------------------------------------------
// Attention_50921132261730 — R17: R15 type-fused qkv + FIXED cp.async tail
// (wait_group 0 on final iterations; R16's rel_err 2.3e-2 was a stage-15
//  RAW race exposed by 1-CTA/SM occupancy). out_gemm tail also hardened.
// ---------------------------------------------------------------------------

constexpr int Bb = 2, Cc = 512, Nn = 2048, HEADS = 16, DHEAD = 64;
constexpr int HDIM = HEADS * DHEAD;    // 1024
constexpr int BH = Bb * HEADS;         // 32

__device__ half g_WqT[Cc * 3 * HDIM];          // [512][3072]
__device__ half g_WoT[HDIM * Cc];              // [1024][512]
__device__ half g_xh [(long)Bb * Cc * Nn];
__device__ half g_qh [(long)BH * DHEAD * Nn];
__device__ half g_kh [(long)BH * DHEAD * Nn];
__device__ half g_vh [(long)BH * DHEAD * Nn];
__device__ half g_aoh[(long)Bb * HDIM * Nn];

__device__ __forceinline__ uint2 pack4h(float4 v) {
    half2 a = __floats2half2_rn(v.x, v.y);
    half2 b = __floats2half2_rn(v.z, v.w);
    uint2 r;
    r.x = *reinterpret_cast<unsigned*>(&a);
    r.y = *reinterpret_cast<unsigned*>(&b);
    return r;
}
__device__ __forceinline__ void cp16(unsigned int s, const void* g) {
    asm volatile("cp.async.cg.shared.global [%0], [%1], 16;" :: "r"(s), "l"(g));
}
__device__ __forceinline__ void ldsm_x4(uint32_t* r, unsigned int a) {
    asm volatile("ldmatrix.sync.aligned.m8n8.x4.shared.b16 {%0,%1,%2,%3}, [%4];"
                 : "=r"(r[0]), "=r"(r[1]), "=r"(r[2]), "=r"(r[3]) : "r"(a));
}
__device__ __forceinline__ void ldsm_x4t(uint32_t* r, unsigned int a) {
    asm volatile("ldmatrix.sync.aligned.m8n8.x4.trans.shared.b16 {%0,%1,%2,%3}, [%4];"
                 : "=r"(r[0]), "=r"(r[1]), "=r"(r[2]), "=r"(r[3]) : "r"(a));
}
__device__ __forceinline__ void mma16816(float* c, const uint32_t* a,
                                         uint32_t b0, uint32_t b1) {
    asm volatile("mma.sync.aligned.m16n8k16.row.col.f32.f16.f16.f32 "
                 "{%0,%1,%2,%3}, {%4,%5,%6,%7}, {%8,%9}, {%0,%1,%2,%3};"
                 : "+f"(c[0]), "+f"(c[1]), "+f"(c[2]), "+f"(c[3])
                 : "r"(a[0]), "r"(a[1]), "r"(a[2]), "r"(a[3]), "r"(b0), "r"(b1));
}

// ---------------------------------------------------------------------------
template<int R, int C>
__global__ void t_f2h(const float* __restrict__ src, half* __restrict__ dst)
{
    __shared__ float tile[32][33];
    const int c0 = blockIdx.x * 32, r0 = blockIdx.y * 32;
    const int tx = threadIdx.x, ty = threadIdx.y;
    #pragma unroll
    for (int i = 0; i < 4; i++)
        tile[ty*4 + i][tx] = src[(long)(r0 + ty*4 + i) * C + c0 + tx];
    __syncthreads();
    #pragma unroll
    for (int i = 0; i < 4; i++)
        dst[(long)(c0 + ty*4 + i) * R + r0 + tx] = __float2half_rn(tile[tx][ty*4 + i]);
}

__global__ void f2h_k(const float* __restrict__ src, half* __restrict__ dst)
{
    long i = ((long)blockIdx.x * 256 + threadIdx.x) * 8;
    float4 a = *(const float4*)(src + i);
    float4 b = *(const float4*)(src + i + 4);
    uint2 pa = pack4h(a), pb = pack4h(b);
    *(uint4*)(dst + i) = make_uint4(pa.x, pa.y, pb.x, pb.y);
}

// ---------------------------------------------------------------------------
// qkv GEMM v2: ONE head per CTA, all 3 types fused (BM=3x64), 256 threads.
// 8 warps of 32x32 per type tile; bf frags shared across types.
// 3-stage cp.async (tail-safe). grid (16, 16, 2). Epilogue: 3 waves.
// ---------------------------------------------------------------------------
constexpr int QLDA = 72, QLDB = 136, QEPILD = 132;
constexpr int QSTG_A  = 32 * QLDA;             // per-type A stage (halfs)
constexpr int QSTG_AT = 3 * QSTG_A;            // all-types A stage
constexpr int QSTG_B  = 32 * QLDB;
constexpr int QKV_SMEM = 3 * (QSTG_AT + QSTG_B) * 2;   // 67,584 B

__global__ void __launch_bounds__(256)
qkv_gemm(const half* __restrict__ WqT, const half* __restrict__ xh,
         const float* __restrict__ q_scale, const float* __restrict__ k_scale,
         half* __restrict__ qh, half* __restrict__ kh, half* __restrict__ vh)
{
    extern __shared__ char smc[];
    half*  As = (half*)smc;                    // [3 stg][3 tt][32*72]
    half*  Bs = As + 3 * QSTG_AT;              // [3 stg][32*136]
    float* Cs = (float*)smc;                   // 64 x 132 epilogue alias

    const int tid = threadIdx.x, wid = tid >> 5;
    const int h = blockIdx.y, n0 = blockIdx.x * 128, b = blockIdx.z;
    const int wm = (wid >> 2) * 32, wn = (wid & 3) * 32;
    const int mbase = h * 64;
    const half* Bx = xh + (long)b * Cc * Nn;
    const unsigned int asb = (unsigned int)__cvta_generic_to_shared(As);
    const unsigned int bsb = (unsigned int)__cvta_generic_to_shared(Bs);

    wmma::fragment<wmma::accumulator,16,16,16,float> acc[3][2][2];
    #pragma unroll
    for (int tt = 0; tt < 3; tt++)
        #pragma unroll
        for (int i = 0; i < 2; i++)
            #pragma unroll
            for (int j = 0; j < 2; j++) wmma::fill_fragment(acc[tt][i][j], 0.f);

    auto ldgsts = [&](int k0, int stg) {
        {   // A: one uint4 per thread per type (32k x 64m each)
            int kk = tid >> 3, mq = tid & 7;
            const half* ap = WqT + (long)(k0+kk)*(3*HDIM) + mbase + mq*8;
            #pragma unroll
            for (int tt = 0; tt < 3; tt++)
                cp16(asb + (stg*QSTG_AT + tt*QSTG_A + kk*QLDA + mq*8)*2,
                     ap + tt*HDIM);
        }
        #pragma unroll
        for (int g = 0; g < 2; g++) {          // B: 32k x 128n = 512 uint4
            int idx = tid + g*256, kk = idx >> 4, nq = idx & 15;
            cp16(bsb + (stg*QSTG_B + kk*QLDB + nq*8)*2,
                 Bx + (long)(k0+kk)*Nn + n0 + nq*8);
        }
        asm volatile("cp.async.commit_group;" ::: "memory");
    };

    ldgsts(0, 0);
    ldgsts(32, 1);

    #pragma unroll 1
    for (int it = 0; it < 16; it++) {
        const int cur = it % 3;
        // Tail-safe wait: last commit is stage 15 at it=13; from it=14 on,
        // wait_group 0 guarantees the consumed stage is complete (R16 bug).
        if (it < 14) asm volatile("cp.async.wait_group 1;" ::: "memory");
        else         asm volatile("cp.async.wait_group 0;" ::: "memory");
        __syncthreads();
        if (it + 2 < 16) ldgsts((it + 2) * 32, (it + 2) % 3);

        #pragma unroll
        for (int kc = 0; kc < 32; kc += 16) {
            wmma::fragment<wmma::matrix_b,16,16,16,half,wmma::row_major> bf[2];
            #pragma unroll
            for (int j = 0; j < 2; j++)
                wmma::load_matrix_sync(bf[j], &Bs[cur*QSTG_B + kc*QLDB + wn + j*16], QLDB);
            #pragma unroll
            for (int tt = 0; tt < 3; tt++) {
                wmma::fragment<wmma::matrix_a,16,16,16,half,wmma::col_major> af[2];
                #pragma unroll
                for (int i = 0; i < 2; i++)
                    wmma::load_matrix_sync(af[i],
                        &As[cur*QSTG_AT + tt*QSTG_A + kc*QLDA + wm + i*16], QLDA);
                #pragma unroll
                for (int j = 0; j < 2; j++)
                    #pragma unroll
                    for (int i = 0; i < 2; i++)
                        wmma::mma_sync(acc[tt][i][j], af[i], bf[j], acc[tt][i][j]);
            }
        }
    }
    __syncthreads();

    // ---- epilogue: 3 waves, one type each, through shared Cs tile ----
    #pragma unroll 1
    for (int tt = 0; tt < 3; tt++) {
        #pragma unroll
        for (int i = 0; i < 2; i++)
            #pragma unroll
            for (int j = 0; j < 2; j++)
                wmma::store_matrix_sync(Cs + (wm + i*16)*QEPILD + wn + j*16,
                                        acc[tt][i][j], QEPILD, wmma::mem_row_major);
        __syncthreads();

        {
            const int j  = tid & 127;
            const int d0 = (tid >> 7) * 32;    // each half of CTA writes 32 d's
            half* dst = (tt == 0 ? qh : (tt == 1 ? kh : vh))
                        + ((long)(b*HEADS + h) * DHEAD) * Nn + n0 + j;
            if (tt == 2) {
                #pragma unroll
                for (int d = 0; d < 32; d++)
                    dst[(long)(d0+d)*Nn] = __float2half_rn(Cs[(d0+d)*QEPILD + j]);
            } else {
                float ss = 0.f;
                #pragma unroll
                for (int d = 0; d < DHEAD; d++) {
                    float t = Cs[d*QEPILD + j];
                    ss += t * t;
                }
                float inv = (tt ? 1.0f : 8.0f) / fmaxf(sqrtf(ss), 1e-12f);
                const float* sc = tt ? k_scale : q_scale;
                #pragma unroll
                for (int d = 0; d < 32; d++)
                    dst[(long)(d0+d)*Nn] =
                        __float2half_rn(Cs[(d0+d)*QEPILD + j] * inv * sc[d0+d]);
            }
        }
        __syncthreads();
    }
}

// ---------------------------------------------------------------------------
// out GEMM (R13 + tail-safe wait)
// ---------------------------------------------------------------------------
constexpr int OLDA = 72, OLDB = 136;
constexpr int OSTG_A = 32 * OLDA;
constexpr int OSTG_B = 32 * OLDB;

__global__ void __launch_bounds__(128, 4)
out_gemm(const half* __restrict__ WoT, const half* __restrict__ Bg,
         float* __restrict__ Cg, const float* __restrict__ bias)
{
    __shared__ half As[3 * OSTG_A];
    __shared__ half Bs[3 * OSTG_B];

    const half* B = Bg + (long)blockIdx.z * HDIM * Nn;
    float*      C = Cg + (long)blockIdx.z * Cc * Nn;
    const int tid = threadIdx.x, wid = tid >> 5;
    const int m0 = blockIdx.y * 64, n0 = blockIdx.x * 128;
    const int wn = wid * 32;
    const unsigned int asb = (unsigned int)__cvta_generic_to_shared(As);
    const unsigned int bsb = (unsigned int)__cvta_generic_to_shared(Bs);

    wmma::fragment<wmma::accumulator,16,16,16,float> acc[4][2];
    {
        float* biasS = (float*)As;
        for (int l = tid; l < 64*20; l += 128)
            biasS[l] = bias[m0 + l/20];
        __syncthreads();
        #pragma unroll
        for (int i = 0; i < 4; i++)
            #pragma unroll
            for (int j = 0; j < 2; j++)
                wmma::load_matrix_sync(acc[i][j], biasS + (i*16)*20, 20,
                                       wmma::mem_row_major);
        __syncthreads();
    }

    auto ldgsts = [&](int k0, int buf) {
        #pragma unroll
        for (int g = 0; g < 2; g++) {
            int idx = tid + g*128, kk = idx >> 3, mq = idx & 7;
            cp16(asb + (buf*OSTG_A + kk*OLDA + mq*8)*2,
                 WoT + (long)(k0+kk)*Cc + m0 + mq*8);
        }
        #pragma unroll
        for (int g = 0; g < 4; g++) {
            int idx = tid + g*128, kk = idx >> 4, nq = idx & 15;
            cp16(bsb + (buf*OSTG_B + kk*OLDB + nq*8)*2,
                 B + (long)(k0+kk)*Nn + n0 + nq*8);
        }
        asm volatile("cp.async.commit_group;" ::: "memory");
    };

    ldgsts(0, 0);
    ldgsts(32, 1);

    #pragma unroll 1
    for (int it = 0; it < 32; it++) {
        const int cur = it % 3;
        if (it < 30) asm volatile("cp.async.wait_group 1;" ::: "memory");
        else         asm volatile("cp.async.wait_group 0;" ::: "memory");
        __syncthreads();
        if (it + 2 < 32) ldgsts((it + 2) * 32, (it + 2) % 3);

        #pragma unroll
        for (int kc = 0; kc < 32; kc += 16) {
            wmma::fragment<wmma::matrix_a,16,16,16,half,wmma::col_major> af[4];
            #pragma unroll
            for (int i = 0; i < 4; i++)
                wmma::load_matrix_sync(af[i], &As[cur*OSTG_A + kc*OLDA + i*16], OLDA);
            #pragma unroll
            for (int j = 0; j < 2; j++) {
                wmma::fragment<wmma::matrix_b,16,16,16,half,wmma::row_major> bf;
                wmma::load_matrix_sync(bf, &Bs[cur*OSTG_B + kc*OLDB + wn + j*16], OLDB);
                #pragma unroll
                for (int i = 0; i < 4; i++)
                    wmma::mma_sync(acc[i][j], af[i], bf, acc[i][j]);
            }
        }
    }

    #pragma unroll
    for (int i = 0; i < 4; i++)
        #pragma unroll
        for (int j = 0; j < 2; j++)
            wmma::store_matrix_sync(C + (long)(m0+i*16)*Nn + n0 + wn + j*16,
                                    acc[i][j], Nn, wmma::mem_row_major);
}

// ---------------------------------------------------------------------------
// Flash attention (unchanged R14): raw m16n8k16, register-resident S/P/O.
// ---------------------------------------------------------------------------
constexpr int FLH  = 136;
constexpr int QLH  = 72;
constexpr int SLDf = 68;
constexpr int KVSTG = 64 * FLH;
constexpr int SF_B = 4 * KVSTG * 2;            // 69632
constexpr int RS_B = SF_B + 4*32*SLDf*4;       // 104448
constexpr int FLASH_SMEM = RS_B + 512;         // 104,960

__global__ void __launch_bounds__(128)
flash_h(const half* __restrict__ qhg, const half* __restrict__ khg,
        const half* __restrict__ vhg, half* __restrict__ aoh)
{
    extern __shared__ char smc[];
    half*  KV = (half*)smc;
    float* Sf = (float*)(smc + SF_B);
    float* rs = (float*)(smc + RS_B);
    half*  Qst = (half*)(smc + SF_B);

    const int tid = threadIdx.x, wid = tid >> 5, lane = tid & 31;
    const int r = wid >> 1, c = wid & 1;
    const int qi0 = blockIdx.x * 64;
    const int bh = blockIdx.y;
    const int b = bh >> 4, h = bh & 15;

    const half* qg = qhg + (long)bh * DHEAD * Nn;
    const half* kg = khg + (long)bh * DHEAD * Nn;
    const half* vg = vhg + (long)bh * DHEAD * Nn;
    const unsigned int kvb = (unsigned int)__cvta_generic_to_shared(KV);
    const unsigned int qsb = (unsigned int)__cvta_generic_to_shared(Qst);

    for (int l = tid; l < 64*8; l += 128) {
        int d = l >> 3, i8 = (l & 7) * 8;
        *(uint4*)&Qst[d*QLH + i8] = *(const uint4*)(qg + (long)d*Nn + qi0 + i8);
    }
    __syncthreads();

    uint32_t qa[2][4][4];
    #pragma unroll
    for (int mi = 0; mi < 2; mi++)
        #pragma unroll
        for (int kc = 0; kc < 4; kc++) {
            int row = kc*16 + (lane & 7) + ((lane >> 4) & 1) * 8;
            int col = r*32 + mi*16 + ((lane >> 3) & 1) * 8;
            ldsm_x4t(qa[mi][kc], qsb + (row*QLH + col) * 2);
        }

    float oc[2][8][4];
    #pragma unroll
    for (int mi = 0; mi < 2; mi++)
        #pragma unroll
        for (int dn = 0; dn < 8; dn++)
            #pragma unroll
            for (int q = 0; q < 4; q++) oc[mi][dn][q] = 0.f;
    float rsum[4] = {0.f, 0.f, 0.f, 0.f};
    __syncthreads();

    auto ldkv = [&](int kt, int buf) {
        #pragma unroll
        for (int g = 0; g < 8; g++) {
            int l = tid + g*128;
            int d = l >> 4, j8 = (l & 15) * 8;
            cp16(kvb + (buf*2*KVSTG + d*FLH + j8)*2, kg + (long)d*Nn + kt + j8);
            cp16(kvb + (buf*2*KVSTG + KVSTG + d*FLH + j8)*2, vg + (long)d*Nn + kt + j8);
        }
        asm volatile("cp.async.commit_group;" ::: "memory");
    };

    ldkv(0, 0);
    const int jbase = c * 64;

    #pragma unroll 1
    for (int t = 0; t < 16; t++) {
        const int cur = t & 1;
        const unsigned int ksB = kvb + (cur*2*KVSTG) * 2;
        const unsigned int vsB = ksB + KVSTG * 2;

        asm volatile("cp.async.wait_group 0;" ::: "memory");
        __syncthreads();
        if (t + 1 < 16) ldkv((t + 1) * 128, cur ^ 1);

        float sc[2][8][4];
        #pragma unroll
        for (int mi = 0; mi < 2; mi++)
            #pragma unroll
            for (int nj = 0; nj < 8; nj++)
                #pragma unroll
                for (int q = 0; q < 4; q++) sc[mi][nj][q] = 0.f;

        #pragma unroll
        for (int kc = 0; kc < 4; kc++) {
            uint32_t kb[4][4];
            #pragma unroll
            for (int njp = 0; njp < 4; njp++) {
                int row = kc*16 + (lane & 7) + ((lane >> 3) & 1) * 8;
                int col = jbase + njp*16 + ((lane >> 4) & 1) * 8;
                ldsm_x4t(kb[njp], ksB + (row*FLH + col) * 2);
            }
            #pragma unroll
            for (int mi = 0; mi < 2; mi++)
                #pragma unroll
                for (int nj = 0; nj < 8; nj++)
                    mma16816(sc[mi][nj], qa[mi][kc],
                             kb[nj >> 1][(nj & 1) * 2], kb[nj >> 1][(nj & 1) * 2 + 1]);
        }

        uint32_t pa[2][4][4];
        #pragma unroll
        for (int mi = 0; mi < 2; mi++)
            #pragma unroll
            for (int nj = 0; nj < 8; nj++) {
                float e0 = __expf(sc[mi][nj][0]);
                float e1 = __expf(sc[mi][nj][1]);
                float e2 = __expf(sc[mi][nj][2]);
                float e3 = __expf(sc[mi][nj][3]);
                rsum[mi*2]   += e0 + e1;
                rsum[mi*2+1] += e2 + e3;
                half2 h01 = __floats2half2_rn(e0, e1);
                half2 h23 = __floats2half2_rn(e2, e3);
                int kj = nj >> 1, lo = (nj & 1) * 2;
                pa[mi][kj][lo]     = *reinterpret_cast<unsigned*>(&h01);
                pa[mi][kj][lo + 1] = *reinterpret_cast<unsigned*>(&h23);
            }

        #pragma unroll
        for (int kj = 0; kj < 4; kj++) {
            uint32_t vb[4][4];
            #pragma unroll
            for (int p = 0; p < 4; p++) {
                int row = p*16 + (lane & 7) + ((lane >> 4) & 1) * 8;
                int col = jbase + kj*16 + ((lane >> 3) & 1) * 8;
                ldsm_x4(vb[p], vsB + (row*FLH + col) * 2);
            }
            #pragma unroll
            for (int mi = 0; mi < 2; mi++)
                #pragma unroll
                for (int dn = 0; dn < 8; dn++)
                    mma16816(oc[mi][dn], pa[mi][kj],
                             vb[dn >> 1][(dn & 1) * 2], vb[dn >> 1][(dn & 1) * 2 + 1]);
        }
    }

    #pragma unroll
    for (int q = 0; q < 4; q++) {
        rsum[q] += __shfl_xor_sync(0xffffffffu, rsum[q], 1);
        rsum[q] += __shfl_xor_sync(0xffffffffu, rsum[q], 2);
    }
    if ((lane & 3) == 0) {
        int rr = lane >> 2;
        rs[wid*32 + rr]      = rsum[0];
        rs[wid*32 + rr + 8]  = rsum[1];
        rs[wid*32 + rr + 16] = rsum[2];
        rs[wid*32 + rr + 24] = rsum[3];
    }

    {
        float* Sw = Sf + wid * (32*SLDf);
        #pragma unroll
        for (int mi = 0; mi < 2; mi++)
            #pragma unroll
            for (int dn = 0; dn < 8; dn++) {
                int row = mi*16 + (lane >> 2);
                int colb = dn*8 + 2*(lane & 3);
                Sw[row*SLDf + colb]       = oc[mi][dn][0];
                Sw[row*SLDf + colb + 1]   = oc[mi][dn][1];
                Sw[(row+8)*SLDf + colb]     = oc[mi][dn][2];
                Sw[(row+8)*SLDf + colb + 1] = oc[mi][dn][3];
            }
    }
    __syncthreads();

    {
        const int i = tid & 63, db = (tid >> 6) * 32;
        const int wA = (i >> 5) * 2, il = i & 31;
        float inv = 1.0f / (rs[wA*32 + il] + rs[(wA+1)*32 + il]);
        const float* SA = Sf + wA*(32*SLDf) + il*SLDf;
        const float* SB = SA + 32*SLDf;
        half* aog = aoh + ((long)b*HDIM + h*DHEAD)*Nn + qi0 + i;
        #pragma unroll
        for (int d = 0; d < 32; d++) {
            int dd = db + d;
            aog[(long)dd*Nn] = __float2half_rn((SA[dd] + SB[dd]) * inv);
        }
    }
}

// ---------------------------------------------------------------------------
extern "C" void kernel_launch(void* const* d_in, const int* in_sizes, int n_in,
                              void* d_out, int out_size)
{
    (void)in_sizes; (void)n_in; (void)out_size;
    const float* x       = (const float*)d_in[0];
    const float* Wqkv    = (const float*)d_in[1];
    const float* q_scale = (const float*)d_in[2];
    const float* k_scale = (const float*)d_in[3];
    const float* Wout    = (const float*)d_in[4];
    const float* bout    = (const float*)d_in[5];
    float* out = (float*)d_out;

    half *WqT, *WoT, *xh, *qh, *kh, *vh, *aoh;
    cudaGetSymbolAddress((void**)&WqT, g_WqT);
    cudaGetSymbolAddress((void**)&WoT, g_WoT);
    cudaGetSymbolAddress((void**)&xh,  g_xh);
    cudaGetSymbolAddress((void**)&qh,  g_qh);
    cudaGetSymbolAddress((void**)&kh,  g_kh);
    cudaGetSymbolAddress((void**)&vh,  g_vh);
    cudaGetSymbolAddress((void**)&aoh, g_aoh);

    cudaFuncSetAttribute(flash_h, cudaFuncAttributeMaxDynamicSharedMemorySize,
                         FLASH_SMEM);
    cudaFuncSetAttribute(qkv_gemm, cudaFuncAttributeMaxDynamicSharedMemorySize,
                         QKV_SMEM);

    // 0) one-time transposed fp16 weights + x convert
    t_f2h<3*HDIM, Cc><<<dim3(Cc/32, 3*HDIM/32), dim3(32,8)>>>(Wqkv, WqT);
    t_f2h<Cc, HDIM><<<dim3(HDIM/32, Cc/32), dim3(32,8)>>>(Wout, WoT);
    f2h_k<<<(int)(((long)Bb*Cc*Nn)/2048), 256>>>(x, xh);

    // 1) type-fused qkv gemm + norm/scale/v epilogue -> qh, kh, vh (fp16)
    qkv_gemm<<<dim3(Nn/128, HEADS, Bb), 256, QKV_SMEM>>>(
        WqT, xh, q_scale, k_scale, qh, kh, vh);

    // 2) flash attention -> aoh (fp16, channel-major)
    flash_h<<<dim3(Nn/64, BH), 128, FLASH_SMEM>>>(qh, kh, vh, aoh);

    // 3) out = WoT^T @ aoh + bout
    out_gemm<<<dim3(Nn/128, Cc/64, Bb), 128>>>(WoT, aoh, out, bout);
}